// round 8
// baseline (speedup 1.0000x reference)
#include <cuda_runtime.h>
#include <math.h>

#define NB   36
#define NB2  72
#define SS   7
#define NOUT (2*NB + 2)  // 74

// One block per batch b, 224 threads = 7 warps, warp w handles s=w.
// Fully barrier-free: per-warp smem staging + __syncwarp only; all
// reductions via shfl butterflies. Lane l owns k=l; lanes 0-3 also k2=32+l.
__global__ __launch_bounds__(224, 4)
void deepwarping_kernel(const float* __restrict__ ll1,   // [B,S,NB]
                        const float* __restrict__ ll2,   // [B,S,NB]
                        const float* __restrict__ inp,   // [B,S,NB]
                        const float* __restrict__ yaw,   // [B]
                        const float* __restrict__ T,     // [61,NB,NB]
                        const float* __restrict__ M,     // [NB,NB] (circulant: row 0 suffices)
                        const float* __restrict__ pop,   // [2,NB]
                        float* __restrict__ out)         // [B,S,NOUT]
{
    const int b    = blockIdx.x;
    const int s    = threadIdx.x >> 5;      // warp id = s (0..6)
    const int lane = threadIdx.x & 31;

    __shared__ float se1 [SS][NB];          // exp(ll1), per-warp row
    __shared__ float se2d[SS][NB2];         // exp(ll2) doubled, per-warp row
    __shared__ float si  [SS][NB];          // inp, per-warp row

    const int base = (b * SS + s) * NB;     // 16B-aligned (36 floats/row)

    // ---- independent front-batched loads ----
    const float yv = __ldg(yaw + b);

    const int  k    = lane;
    const int  k2   = 32 + (lane & 3);      // always in [32,35]
    const bool has2 = lane < 4;

    const float eMk   = __expf(__ldg(M + k));        // circulant: M[0][k]
    const float eMk2  = __expf(__ldg(M + k2));
    const float popc  = __ldg(pop + k);
    const float pops  = __ldg(pop + NB + k);
    const float popc2 = __ldg(pop + k2);
    const float pops2 = __ldg(pop + NB + k2);

    // per-warp staging: lanes 0-8 ll1, 9-17 ll2(doubled), 18-26 inp
    if (lane < 9) {
        float4 a = ((const float4*)(ll1 + base))[lane];
        ((float4*)se1[s])[lane] =
            make_float4(__expf(a.x), __expf(a.y), __expf(a.z), __expf(a.w));
    } else if (lane < 18) {
        const int q = lane - 9;
        float4 c = ((const float4*)(ll2 + base))[q];
        float4 e = make_float4(__expf(c.x), __expf(c.y), __expf(c.z), __expf(c.w));
        ((float4*)(se2d[s]))[q]      = e;
        ((float4*)(se2d[s] + NB))[q] = e;
    } else if (lane < 27) {
        const int q = lane - 18;
        ((float4*)si[s])[q] = ((const float4*)(inp + base))[q];
    }

    // dependent chain: yaw -> idx -> T rows (overlaps the staging above)
    const int idx = 30 + (int)rintf(yv * (180.0f / 3.14159265358979323846f));
    const float4* Trow  = (const float4*)(T + idx * NB * NB + k  * NB);
    const float4* Trow2 = (const float4*)(T + idx * NB * NB + k2 * NB);

    __syncwarp();

    // ---- s_k (and s_k2 fused) : circular cross-correlation ----
    float sa0 = 0.f, sa1 = 0.f, sb0 = 0.f, sb1 = 0.f;
    #pragma unroll
    for (int i = 0; i < NB; i += 2) {
        const float e1a = se1[s][i];
        const float e1b = se1[s][i + 1];
        sa0 += e1a * se2d[s][i + k];
        sa1 += e1b * se2d[s][i + 1 + k];
        sb0 += e1a * se2d[s][i + k2];
        sb1 += e1b * se2d[s][i + 1 + k2];
    }
    const float acc  = (sa0 + sa1) * eMk;
    const float acc2 = (sb0 + sb1) * eMk2;

    // ---- warped matvec (both rows fused; T from global, si broadcast LDS) ----
    float w0 = 0.f, w1 = 0.f, w2 = 0.f, w3 = 0.f;
    float u0 = 0.f, u1 = 0.f, u2 = 0.f, u3 = 0.f;
    #pragma unroll
    for (int q = 0; q < NB / 4; q++) {
        const float4 sv  = ((const float4*)si[s])[q];
        const float4 tv  = __ldg(Trow  + q);
        const float4 tv2 = __ldg(Trow2 + q);
        w0 += tv.x  * sv.x;  w1 += tv.y  * sv.y;
        w2 += tv.z  * sv.z;  w3 += tv.w  * sv.w;
        u0 += tv2.x * sv.x;  u1 += tv2.y * sv.y;
        u2 += tv2.z * sv.z;  u3 += tv2.w * sv.w;
    }
    const float wv  = (w0 + w1) + (w2 + w3);
    const float wv2 = (u0 + u1) + (u2 + u3);

    // ---- warp reductions: tot, v0, v1 (fused butterflies) ----
    float tp = acc + (has2 ? acc2 : 0.f);
    float v0 = acc * popc + (has2 ? acc2 * popc2 : 0.f);
    float v1 = acc * pops + (has2 ? acc2 * pops2 : 0.f);
    #pragma unroll
    for (int off = 16; off; off >>= 1) {
        tp += __shfl_xor_sync(0xFFFFFFFFu, tp, off);
        v0 += __shfl_xor_sync(0xFFFFFFFFu, v0, off);
        v1 += __shfl_xor_sync(0xFFFFFFFFu, v1, off);
    }

    // ---- outputs ----
    float* o = out + (b * SS + s) * NOUT;
    const float lt = __logf(tp);
    o[k]          = wv;
    o[NB + 2 + k] = __logf(acc) - lt;
    if (has2) {
        o[k2]          = wv2;
        o[NB + 2 + k2] = __logf(acc2) - lt;
    }
    if (lane == 0) {
        const float inv = 1.0f / tp;
        float a0 = v0 * inv + 1e-8f;
        float a1 = v1 * inv;
        const float n = sqrtf(a0 * a0 + a1 * a1);
        a0 /= n; a1 /= n;
        o[NB]     = fminf(fmaxf(a0, -1.0f), 1.0f);
        o[NB + 1] = fminf(fmaxf(a1, -1.0f), 1.0f);
    }
}

extern "C" void kernel_launch(void* const* d_in, const int* in_sizes, int n_in,
                              void* d_out, int out_size)
{
    const float* ll1 = (const float*)d_in[0];   // loglikelihood1 [128,7,36]
    const float* ll2 = (const float*)d_in[1];   // loglikelihood2 [128,7,36]
    const float* inp = (const float*)d_in[2];   // inp            [128,7,36]
    const float* yaw = (const float*)d_in[3];   // yaw            [128]
    const float* T   = (const float*)d_in[4];   // transform_matrices [61,36,36]
    const float* M   = (const float*)d_in[5];   // logprior_rotate_matrix [36,36] (circulant)
    // d_in[6] = template_log — equivalent to k=(j-i)%36 selector; unused
    const float* pop = (const float*)d_in[7];   // population_vector [2,36]
    float* out = (float*)d_out;

    const int B = in_sizes[3];                  // 128
    deepwarping_kernel<<<B, SS * 32>>>(ll1, ll2, inp, yaw, T, M, pop, out);
}

// round 10
// speedup vs baseline: 1.1171x; 1.1171x over previous
#include <cuda_runtime.h>
#include <math.h>

#define NB   36
#define NB2  72
#define NBP  37          // padded sT row stride -> conflict-free per-lane row reads
#define SS   7
#define NOUT (2*NB + 2)  // 74

// One block per batch b, 224 threads = 7 warps; warp w handles s=w.
// Lane l owns k=l; lanes 0-3 also own k2=32+l.
// T[idx] staged cooperatively (324 float4, strided over 224 threads) into
// padded smem; consumed after the single __syncthreads, which is hidden
// behind the ssum/shuffle/logpost phase.
__global__ __launch_bounds__(224, 4)
void deepwarping_kernel(const float* __restrict__ ll1,   // [B,S,NB]
                        const float* __restrict__ ll2,   // [B,S,NB]
                        const float* __restrict__ inp,   // [B,S,NB]
                        const float* __restrict__ yaw,   // [B]
                        const float* __restrict__ T,     // [61,NB,NB]
                        const float* __restrict__ M,     // [NB,NB] (circulant)
                        const float* __restrict__ pop,   // [2,NB]
                        float* __restrict__ out)         // [B,S,NOUT]
{
    const int b    = blockIdx.x;
    const int tid  = threadIdx.x;
    const int s    = tid >> 5;              // warp id = s (0..6)
    const int lane = tid & 31;

    __shared__ float sT  [NB * NBP];        // yaw-selected transform, padded rows
    __shared__ float se1 [SS][NB];          // exp(ll1), per-warp row
    __shared__ float se2d[SS][NB2];         // exp(ll2) doubled, per-warp row
    __shared__ float si  [SS][NB];          // inp, per-warp row

    const int base = (b * SS + s) * NB;     // 16B-aligned

    // ---- independent front-batched loads ----
    const float yv = __ldg(yaw + b);

    const int  k    = lane;
    const int  k2   = 32 + (lane & 3);
    const bool has2 = lane < 4;

    const float eMk   = __expf(__ldg(M + k));     // circulant: M[0][k]
    const float eMk2  = __expf(__ldg(M + k2));
    const float popc  = __ldg(pop + k);
    const float pops  = __ldg(pop + NB + k);
    const float popc2 = __ldg(pop + k2);
    const float pops2 = __ldg(pop + NB + k2);

    // per-warp input staging: lanes 0-8 ll1, 9-17 ll2(doubled), 18-26 inp
    if (lane < 9) {
        float4 a = ((const float4*)(ll1 + base))[lane];
        ((float4*)se1[s])[lane] =
            make_float4(__expf(a.x), __expf(a.y), __expf(a.z), __expf(a.w));
    } else if (lane < 18) {
        const int q = lane - 9;
        float4 c = ((const float4*)(ll2 + base))[q];
        float4 e = make_float4(__expf(c.x), __expf(c.y), __expf(c.z), __expf(c.w));
        ((float4*)(se2d[s]))[q]      = e;
        ((float4*)(se2d[s] + NB))[q] = e;
    } else if (lane < 27) {
        const int q = lane - 18;
        ((float4*)si[s])[q] = ((const float4*)(inp + base))[q];
    }

    // block-wide cooperative T staging: 324 float4, strided over 224 threads
    const int idx = 30 + (int)rintf(yv * (180.0f / 3.14159265358979323846f));
    {
        const float4* T4 = (const float4*)(T + idx * NB * NB);
        #pragma unroll
        for (int t = tid; t < (NB * NB) / 4; t += 224) {   // 324 total
            const float4 v = T4[t];
            const int e = t * 4;
            const int r0 = e / NB,       c0 = e - r0 * NB;
            const int r1 = (e + 1) / NB, c1 = (e + 1) - r1 * NB;
            const int r2 = (e + 2) / NB, c2 = (e + 2) - r2 * NB;
            const int r3 = (e + 3) / NB, c3 = (e + 3) - r3 * NB;
            sT[r0 * NBP + c0] = v.x;
            sT[r1 * NBP + c1] = v.y;
            sT[r2 * NBP + c2] = v.z;
            sT[r3 * NBP + c3] = v.w;
        }
    }

    __syncwarp();   // per-warp input rows ready

    // ---- s_k (and s_k2) : circular cross-correlation, wrap-free ----
    float sa0 = 0.f, sa1 = 0.f, sb0 = 0.f, sb1 = 0.f;
    #pragma unroll
    for (int i = 0; i < NB; i += 2) {
        const float e1a = se1[s][i];
        const float e1b = se1[s][i + 1];
        sa0 += e1a * se2d[s][i + k];
        sa1 += e1b * se2d[s][i + 1 + k];
        sb0 += e1a * se2d[s][i + k2];
        sb1 += e1b * se2d[s][i + 1 + k2];
    }
    const float acc  = (sa0 + sa1) * eMk;
    const float acc2 = (sb0 + sb1) * eMk2;

    // ---- warp reductions: tot, v0, v1 (fused butterflies) ----
    float tp = acc + (has2 ? acc2 : 0.f);
    float v0 = acc * popc + (has2 ? acc2 * popc2 : 0.f);
    float v1 = acc * pops + (has2 ? acc2 * pops2 : 0.f);
    #pragma unroll
    for (int off = 16; off; off >>= 1) {
        tp += __shfl_xor_sync(0xFFFFFFFFu, tp, off);
        v0 += __shfl_xor_sync(0xFFFFFFFFu, v0, off);
        v1 += __shfl_xor_sync(0xFFFFFFFFu, v1, off);
    }

    // ---- logpost + vec outputs (independent of T) ----
    float* o = out + (b * SS + s) * NOUT;
    const float lt = __logf(tp);
    o[NB + 2 + k] = __logf(acc) - lt;
    if (has2) o[NB + 2 + k2] = __logf(acc2) - lt;
    if (lane == 0) {
        const float inv = 1.0f / tp;
        float a0 = v0 * inv + 1e-8f;
        float a1 = v1 * inv;
        const float n = sqrtf(a0 * a0 + a1 * a1);
        a0 /= n; a1 /= n;
        o[NB]     = fminf(fmaxf(a0, -1.0f), 1.0f);
        o[NB + 1] = fminf(fmaxf(a1, -1.0f), 1.0f);
    }

    __syncthreads();    // T staging complete (latency hidden by the work above)

    // ---- warped matvec from padded smem: lane reads row k (stride 37, no conflicts) ----
    {
        float w0 = 0.f, w1 = 0.f, w2 = 0.f, w3 = 0.f;
        float u0 = 0.f, u1 = 0.f, u2 = 0.f, u3 = 0.f;
        const int kb = k * NBP, kb2 = k2 * NBP;
        #pragma unroll
        for (int j = 0; j < NB; j += 4) {
            const float s0 = si[s][j], s1v = si[s][j+1], s2v = si[s][j+2], s3v = si[s][j+3];
            w0 += sT[kb  + j    ] * s0;
            w1 += sT[kb  + j + 1] * s1v;
            w2 += sT[kb  + j + 2] * s2v;
            w3 += sT[kb  + j + 3] * s3v;
            u0 += sT[kb2 + j    ] * s0;
            u1 += sT[kb2 + j + 1] * s1v;
            u2 += sT[kb2 + j + 2] * s2v;
            u3 += sT[kb2 + j + 3] * s3v;
        }
        o[k] = (w0 + w1) + (w2 + w3);
        if (has2) o[k2] = (u0 + u1) + (u2 + u3);
    }
}

extern "C" void kernel_launch(void* const* d_in, const int* in_sizes, int n_in,
                              void* d_out, int out_size)
{
    const float* ll1 = (const float*)d_in[0];   // loglikelihood1 [128,7,36]
    const float* ll2 = (const float*)d_in[1];   // loglikelihood2 [128,7,36]
    const float* inp = (const float*)d_in[2];   // inp            [128,7,36]
    const float* yaw = (const float*)d_in[3];   // yaw            [128]
    const float* T   = (const float*)d_in[4];   // transform_matrices [61,36,36]
    const float* M   = (const float*)d_in[5];   // logprior_rotate_matrix [36,36] (circulant)
    // d_in[6] = template_log — equivalent to k=(j-i)%36 selector; unused
    const float* pop = (const float*)d_in[7];   // population_vector [2,36]
    float* out = (float*)d_out;

    const int B = in_sizes[3];                  // 128
    deepwarping_kernel<<<B, SS * 32>>>(ll1, ll2, inp, yaw, T, M, pop, out);
}